// round 1
// baseline (speedup 1.0000x reference)
#include <cuda_runtime.h>
#include <math.h>

// ---------------- problem constants ----------------
constexpr int kB   = 2;
constexpr int kT   = 98304;
constexpr int kS   = 128;
constexpr int kHOP = 768;
constexpr int kNCB = 14;
constexpr int kDIM = 512;
constexpr int kVOC = 1024;
constexpr int kCH3 = kNCB * kDIM;   // 7168
constexpr long kL  = 97537;         // decoder output length
constexpr int kBS  = kB * kS;       // 256

// ---------------- device scratch (no allocs allowed) ----------------
__device__ float g_h2  [kBS * 512];          // encoder conv2 output [bs][c2]
__device__ float g_X   [kBS * 1536];         // im2col for enc conv3
__device__ float g_C1  [kBS * kCH3];         // enc conv3 raw
__device__ float g_emb [kNCB * kBS * kDIM];  // [k][bs][d]
__device__ float g_sc  [(long)kNCB * kBS * kVOC]; // VQ dot products
__device__ float g_cbn [kNCB * kVOC];        // ||codebook||^2
__device__ int   g_code[kNCB * kBS];
__device__ float g_q   [kBS * kCH3];         // quantized vectors [bs][k*512+d]
__device__ float g_C2  [kBS * 2560];         // conv_t specials raw: [bs][o*5+rr]
__device__ float g_awin[kBS * 13 * 512];     // a window: [bs][off+6][c]
__device__ float g_W2r [256 * 2560];         // dw2 rearranged: [c'][jj*512+c]
__device__ float g_C3  [kBS * 9 * 256];      // conv2 specials raw: [bs*9+r2+4][c']
__device__ float g_bg2 [256];
__device__ float g_outbg;

// ---------------- fused encoder conv1+conv2 ----------------
// h2[bs][c2] = relu(eb2 + sum_{c1,j} ew2[c2,c1,j] * relu1(b, 768s-2+j, c1))
__global__ __launch_bounds__(256) void k_enc12(
    const float* __restrict__ audio, const float* __restrict__ ew1,
    const float* __restrict__ eb1,   const float* __restrict__ ew2,
    const float* __restrict__ eb2) {
    int bs = blockIdx.x; int b = bs / kS; int s = bs % kS;
    __shared__ float s1[1280]; // [c1*5 + j]
    int tid = threadIdx.x;
    int c1 = tid;
    float wv[7];
    #pragma unroll
    for (int i = 0; i < 7; i++) wv[i] = ew1[c1 * 7 + i];
    float bias = eb1[c1];
    const float* au = audio + (long)b * kT;
    #pragma unroll
    for (int j = 0; j < 5; j++) {
        int p = s * kHOP - 2 + j;
        float v = 0.f;
        if (p >= 0 && p < kT) {  // conv2 zero-padding
            float acc = bias;
            #pragma unroll
            for (int i = 0; i < 7; i++) {
                int x = p - 3 + i;
                float a = (x >= 0 && x < kT) ? au[x] : 0.f;
                acc = fmaf(wv[i], a, acc);
            }
            v = fmaxf(acc, 0.f);
        }
        s1[c1 * 5 + j] = v;
    }
    __syncthreads();
    int lane = tid & 31, warp = tid >> 5;
    for (int ii = 0; ii < 64; ii++) {
        int c2 = warp * 64 + ii;
        const float* wr = ew2 + (long)c2 * 1280;
        float acc = 0.f;
        #pragma unroll 4
        for (int kk = lane; kk < 1280; kk += 32)
            acc = fmaf(wr[kk], s1[kk], acc);
        #pragma unroll
        for (int o = 16; o > 0; o >>= 1) acc += __shfl_down_sync(0xffffffffu, acc, o);
        if (lane == 0) g_h2[(long)bs * 512 + c2] = fmaxf(acc + eb2[c2], 0.f);
    }
}

// ---------------- im2col for enc conv3 (k=3, p=1) ----------------
__global__ void k_im2col() {
    int m = blockIdx.x; int b = m / kS, s = m % kS;
    for (int kk = threadIdx.x; kk < 1536; kk += blockDim.x) {
        int c2 = kk / 3, j = kk % 3;
        int s2 = s - 1 + j;
        float v = (s2 >= 0 && s2 < kS) ? g_h2[(long)(b * kS + s2) * 512 + c2] : 0.f;
        g_X[(long)m * 1536 + kk] = v;
    }
}

// ---------------- generic fp32 tiled GEMMs (64x64x16, 4x4/thread) ----------------
// Row mapping: A row m starts at A + (m/adiv)*aout + (m%adiv)*ain (enables
// overlapping-window "virtual im2col" for the decoder conv2 GEMM).
#define GEMM_PROLOG                                                          \
    __shared__ float As[16][68];                                             \
    __shared__ float Bs[16][68];                                             \
    int tid = threadIdx.x;                                                   \
    int m0 = blockIdx.y * 64, n0 = blockIdx.x * 64;                          \
    int tx = tid & 15, ty = tid >> 4;                                        \
    int lk = tid & 15, lm = tid >> 4;                                        \
    float acc[4][4] = {};                                                    \
    long arow[4];                                                            \
    _Pragma("unroll")                                                        \
    for (int i = 0; i < 4; i++) {                                            \
        int m = m0 + lm + i * 16;                                            \
        arow[i] = (long)(m / adiv) * aout + (long)(m % adiv) * ain;          \
    }

#define GEMM_COMPUTE                                                         \
        __syncthreads();                                                     \
        _Pragma("unroll")                                                    \
        for (int k = 0; k < 16; k++) {                                       \
            float4 av = *(const float4*)&As[k][ty * 4];                      \
            float4 bv = *(const float4*)&Bs[k][tx * 4];                      \
            float a4[4] = {av.x, av.y, av.z, av.w};                          \
            float b4[4] = {bv.x, bv.y, bv.z, bv.w};                          \
            _Pragma("unroll")                                                \
            for (int i = 0; i < 4; i++)                                      \
                _Pragma("unroll")                                            \
                for (int j = 0; j < 4; j++)                                  \
                    acc[i][j] = fmaf(a4[i], b4[j], acc[i][j]);               \
        }                                                                    \
        __syncthreads();

#define GEMM_EPILOG                                                          \
    _Pragma("unroll")                                                        \
    for (int i = 0; i < 4; i++) {                                            \
        float4 v = make_float4(acc[i][0], acc[i][1], acc[i][2], acc[i][3]);  \
        *(float4*)&C[(long)(m0 + ty * 4 + i) * N + n0 + tx * 4] = v;         \
    }

// C[m,n] = sum_k Arow(m)[k] * B[n*K + k]   (B row-major [N,K])
__global__ __launch_bounds__(256) void gemm_nt(
    const float* __restrict__ A, const float* __restrict__ Bm,
    float* __restrict__ C, int N, int K,
    int adiv, long aout, long ain, long bsA, long bsB, long bsC) {
    A += blockIdx.z * bsA; Bm += blockIdx.z * bsB; C += blockIdx.z * bsC;
    GEMM_PROLOG
    for (int k0 = 0; k0 < K; k0 += 16) {
        #pragma unroll
        for (int i = 0; i < 4; i++)
            As[lk][lm + i * 16] = A[arow[i] + k0 + lk];
        #pragma unroll
        for (int i = 0; i < 4; i++)
            Bs[lk][lm + i * 16] = Bm[(long)(n0 + lm + i * 16) * K + k0 + lk];
        GEMM_COMPUTE
    }
    GEMM_EPILOG
}

// C[m,n] = sum_k Arow(m)[k] * B[k*N + n]   (B row-major [K,N])
__global__ __launch_bounds__(256) void gemm_nn(
    const float* __restrict__ A, const float* __restrict__ Bm,
    float* __restrict__ C, int N, int K,
    int adiv, long aout, long ain) {
    GEMM_PROLOG
    for (int k0 = 0; k0 < K; k0 += 16) {
        #pragma unroll
        for (int i = 0; i < 4; i++)
            As[lk][lm + i * 16] = A[arow[i] + k0 + lk];
        #pragma unroll
        for (int i = 0; i < 4; i++) {
            int kk = (tid >> 6) + i * 4;
            int nn = tid & 63;
            Bs[kk][nn] = Bm[(long)(k0 + kk) * N + n0 + nn];
        }
        GEMM_COMPUTE
    }
    GEMM_EPILOG
}

// ---------------- VQ helpers ----------------
__global__ void k_embbias(const float* __restrict__ eb3) {
    int m = blockIdx.x;
    for (int n = threadIdx.x; n < kCH3; n += blockDim.x) {
        int k = n >> 9, d = n & 511;
        g_emb[((long)k * kBS + m) * kDIM + d] = g_C1[(long)m * kCH3 + n] + eb3[n];
    }
}

__global__ void k_cbnorm(const float* __restrict__ cb) {
    int row = blockIdx.x * 8 + (threadIdx.x >> 5);
    int lane = threadIdx.x & 31;
    const float* p = cb + (long)row * kDIM;
    float acc = 0.f;
    for (int d = lane; d < kDIM; d += 32) { float v = p[d]; acc = fmaf(v, v, acc); }
    #pragma unroll
    for (int o = 16; o > 0; o >>= 1) acc += __shfl_down_sync(0xffffffffu, acc, o);
    if (!lane) g_cbn[row] = acc;
}

__global__ void k_argmin() {
    int row = blockIdx.x;                 // k*kBS + m
    int k = row / kBS;
    const float* sc = g_sc + (long)row * kVOC;
    const float* cn = g_cbn + k * kVOC;
    float best = 3.4e38f; int bi = 0;
    for (int v = threadIdx.x; v < kVOC; v += 256) {
        float d = cn[v] - 2.f * sc[v];
        if (d < best) { best = d; bi = v; }  // v strictly increasing per thread
    }
    __shared__ float sv[256]; __shared__ int si[256];
    sv[threadIdx.x] = best; si[threadIdx.x] = bi;
    __syncthreads();
    for (int st = 128; st > 0; st >>= 1) {
        if (threadIdx.x < st) {
            float o = sv[threadIdx.x + st]; int oi = si[threadIdx.x + st];
            if (o < sv[threadIdx.x] || (o == sv[threadIdx.x] && oi < si[threadIdx.x])) {
                sv[threadIdx.x] = o; si[threadIdx.x] = oi;
            }
        }
        __syncthreads();
    }
    if (!threadIdx.x) g_code[row] = si[0];
}

__global__ void k_gather(const float* __restrict__ cb) {
    int m = blockIdx.x;
    for (int n = threadIdx.x; n < kCH3; n += blockDim.x) {
        int k = n >> 9, d = n & 511;
        int code = g_code[k * kBS + m];
        g_q[(long)m * kCH3 + n] = cb[((long)k * kVOC + code) * kDIM + d];
    }
}

// ---------------- decoder helpers ----------------
// W2r[c'][jj*512+c] = dw2[c'][c][jj]  (K-ordering matched to awin windows)
__global__ void k_w2r(const float* __restrict__ dw2) {
    long i = (long)blockIdx.x * blockDim.x + threadIdx.x;
    if (i < 256L * 2560) {
        int cp = (int)(i / 2560), r = (int)(i % 2560);
        int jj = r / 512, c = r % 512;
        g_W2r[i] = dw2[(long)cp * 2560 + c * 5 + jj];
    }
}

// a-window around 768s: off in [-6,6]; special relu(conv_t) for |off|<=2, else bg1, 0 OOB
__global__ void k_awin(const float* __restrict__ db1) {
    int m = blockIdx.x; int s = m % kS;
    for (int i = threadIdx.x; i < 13 * 512; i += blockDim.x) {
        int off = i / 512 - 6; int o = i & 511;
        long t = (long)s * kHOP + off;
        float v = 0.f;
        if (t >= 0 && t < kL) {
            if (off >= -2 && off <= 2)
                v = fmaxf(g_C2[(long)m * 2560 + o * 5 + (off + 2)] + db1[o], 0.f);
            else
                v = fmaxf(db1[o], 0.f);
        }
        g_awin[(long)m * 6656 + i] = v;
    }
}

// background through conv2: bg2[c'] = relu(db2 + sum dw2 * relu(db1))
__global__ void k_bg2(const float* __restrict__ dw2, const float* __restrict__ db1,
                      const float* __restrict__ db2) {
    int cp = blockIdx.x, tid = threadIdx.x;
    float acc = 0.f;
    for (int kk = tid; kk < 2560; kk += 256)
        acc = fmaf(dw2[(long)cp * 2560 + kk], fmaxf(db1[kk / 5], 0.f), acc);
    __shared__ float red[256];
    red[tid] = acc; __syncthreads();
    for (int st = 128; st; st >>= 1) { if (tid < st) red[tid] += red[tid + st]; __syncthreads(); }
    if (!tid) g_bg2[cp] = fmaxf(red[0] + db2[cp], 0.f);
}

__global__ void k_outbg(const float* __restrict__ dw3, const float* __restrict__ db3) {
    __shared__ float red[256];
    int c = threadIdx.x;
    float a = 0.f;
    #pragma unroll
    for (int j = 0; j < 7; j++) a += dw3[c * 7 + j];
    red[c] = a * g_bg2[c];
    __syncthreads();
    for (int st = 128; st; st >>= 1) { if (c < st) red[c] += red[c + st]; __syncthreads(); }
    if (!c) g_outbg = tanhf(red[0] + db3[0]);
}

__global__ void k_fill(float* __restrict__ out, long n) {
    long i = (long)blockIdx.x * 256 + threadIdx.x;
    if (i < n) out[i] = g_outbg;
}

// final conv3 at the 15 special positions per (b,s)
__global__ __launch_bounds__(256) void k_final(
    float* __restrict__ out, const float* __restrict__ db2,
    const float* __restrict__ dw3, const float* __restrict__ db3) {
    int m = blockIdx.x; int b = m / kS, s = m % kS;
    int tid = threadIdx.x;
    int g = tid >> 4, l = tid & 15;       // 16 groups of 16; group = r3 index
    int r3 = g - 7;
    long t = (long)s * kHOP + r3;
    bool active = (g < 15) && t >= 0 && t < kL;
    float acc = 0.f;
    if (g < 15) {
        for (int c = l; c < 256; c += 16) {
            #pragma unroll
            for (int j = 0; j < 7; j++) {
                int off = r3 - 3 + j;
                long tt = (long)s * kHOP + off;
                float a2;
                if (tt < 0 || tt >= kL) a2 = 0.f;
                else if (off >= -4 && off <= 4)
                    a2 = fmaxf(g_C3[((long)m * 9 + off + 4) * 256 + c] + db2[c], 0.f);
                else a2 = g_bg2[c];
                acc = fmaf(dw3[c * 7 + j], a2, acc);
            }
        }
    }
    #pragma unroll
    for (int o = 8; o > 0; o >>= 1) acc += __shfl_down_sync(0xffffffffu, acc, o, 16);
    if (active && l == 0) out[(long)b * kL + t] = tanhf(acc + db3[0]);
}

// ---------------- launch ----------------
extern "C" void kernel_launch(void* const* d_in, const int* in_sizes, int n_in,
                              void* d_out, int out_size) {
    const float* audio = (const float*)d_in[0];
    const float* cb    = (const float*)d_in[1];
    const float* ew1   = (const float*)d_in[2];
    const float* eb1   = (const float*)d_in[3];
    const float* ew2   = (const float*)d_in[4];
    const float* eb2   = (const float*)d_in[5];
    const float* ew3   = (const float*)d_in[6];
    const float* eb3   = (const float*)d_in[7];
    const float* dw1   = (const float*)d_in[8];
    const float* db1   = (const float*)d_in[9];
    const float* dw2   = (const float*)d_in[10];
    const float* db2   = (const float*)d_in[11];
    const float* dw3   = (const float*)d_in[12];
    const float* db3   = (const float*)d_in[13];
    float* out = (float*)d_out;

    void *pX, *pC1, *pEmb, *pSc, *pQ, *pC2, *pAwin, *pW2r, *pC3;
    cudaGetSymbolAddress(&pX, g_X);
    cudaGetSymbolAddress(&pC1, g_C1);
    cudaGetSymbolAddress(&pEmb, g_emb);
    cudaGetSymbolAddress(&pSc, g_sc);
    cudaGetSymbolAddress(&pQ, g_q);
    cudaGetSymbolAddress(&pC2, g_C2);
    cudaGetSymbolAddress(&pAwin, g_awin);
    cudaGetSymbolAddress(&pW2r, g_W2r);
    cudaGetSymbolAddress(&pC3, g_C3);

    const int BIG = 1 << 30;

    // encoder
    k_enc12<<<kBS, 256>>>(audio, ew1, eb1, ew2, eb2);
    k_im2col<<<kBS, 256>>>();
    gemm_nt<<<dim3(kCH3 / 64, kBS / 64, 1), 256>>>(
        (const float*)pX, ew3, (float*)pC1, kCH3, 1536, BIG, 0, 1536, 0, 0, 0);
    k_embbias<<<kBS, 256>>>(eb3);

    // VQ
    k_cbnorm<<<kNCB * kVOC / 8, 256>>>(cb);
    gemm_nt<<<dim3(kVOC / 64, kBS / 64, kNCB), 256>>>(
        (const float*)pEmb, cb, (float*)pSc, kVOC, kDIM, BIG, 0, kDIM,
        (long)kBS * kDIM, (long)kVOC * kDIM, (long)kBS * kVOC);
    k_argmin<<<kNCB * kBS, 256>>>();
    k_gather<<<kBS, 256>>>(cb);

    // decoder: conv_transpose specials (dw1 as-is is the NN GEMM B matrix)
    gemm_nn<<<dim3(2560 / 64, kBS / 64, 1), 256>>>(
        (const float*)pQ, dw1, (float*)pC2, 2560, kCH3, BIG, 0, kCH3);

    // decoder conv2 specials over sliding windows
    k_w2r<<<(256 * 2560 + 255) / 256, 256>>>(dw2);
    k_awin<<<kBS, 256>>>(db1);
    gemm_nt<<<dim3(256 / 64, kBS * 9 / 64, 1), 256>>>(
        (const float*)pAwin, (const float*)pW2r, (float*)pC3, 256, 2560,
        9, 6656, 512, 0, 0, 0);

    // background + final conv3 specials
    k_bg2<<<256, 256>>>(dw2, db1, db2);
    k_outbg<<<1, 256>>>(dw3, db3);
    k_fill<<<(int)((kB * kL + 255) / 256), 256>>>(out, kB * kL);
    k_final<<<kBS, 256>>>(out, db2, dw3, db3);
}

// round 2
// speedup vs baseline: 1.3228x; 1.3228x over previous
#include <cuda_runtime.h>
#include <math.h>

typedef unsigned long long ull;

// ---------------- problem constants ----------------
constexpr int kB   = 2;
constexpr int kT   = 98304;
constexpr int kS   = 128;
constexpr int kHOP = 768;
constexpr int kNCB = 14;
constexpr int kDIM = 512;
constexpr int kVOC = 1024;
constexpr int kCH3 = kNCB * kDIM;   // 7168
constexpr long kL  = 97537;         // decoder output length
constexpr int kBS  = kB * kS;       // 256
constexpr int kSPLIT = 4;           // conv_t split-K factor

// ---------------- device scratch (no allocs allowed) ----------------
__device__ float g_h2  [kBS * 512];
__device__ float g_X   [kBS * 1536];
__device__ float g_C1  [kBS * kCH3];
__device__ float g_emb [kNCB * kBS * kDIM];
__device__ float g_sc  [(long)kNCB * kBS * kVOC];
__device__ float g_cbn [kNCB * kVOC];
__device__ int   g_code[kNCB * kBS];
__device__ float g_q   [kBS * kCH3];
__device__ float g_C2p [kSPLIT * kBS * 2560];   // conv_t split-K partials
__device__ float g_awin[kBS * 13 * 512];
__device__ float g_W2r [256 * 2560];
__device__ float g_C3  [kBS * 9 * 256];
__device__ float g_bg2 [256];
__device__ float g_outbg;

// ---------------- f32x2 helpers ----------------
__device__ __forceinline__ void fma2(ull& acc, ull a, ull b) {
    asm("fma.rn.f32x2 %0, %1, %2, %0;" : "+l"(acc) : "l"(a), "l"(b));
}
__device__ __forceinline__ ull dup2(float x) {
    ull r; asm("mov.b64 %0, {%1, %1};" : "=l"(r) : "f"(x)); return r;
}
__device__ __forceinline__ void unpack2(ull v, float& lo, float& hi) {
    asm("mov.b64 {%0, %1}, %2;" : "=f"(lo), "=f"(hi) : "l"(v));
}

// ---------------- fused encoder conv1+conv2 ----------------
__global__ __launch_bounds__(256) void k_enc12(
    const float* __restrict__ audio, const float* __restrict__ ew1,
    const float* __restrict__ eb1,   const float* __restrict__ ew2,
    const float* __restrict__ eb2) {
    int bs = blockIdx.x; int b = bs / kS; int s = bs % kS;
    __shared__ float s1[1280];
    int tid = threadIdx.x;
    int c1 = tid;
    float wv[7];
    #pragma unroll
    for (int i = 0; i < 7; i++) wv[i] = ew1[c1 * 7 + i];
    float bias = eb1[c1];
    const float* au = audio + (long)b * kT;
    #pragma unroll
    for (int j = 0; j < 5; j++) {
        int p = s * kHOP - 2 + j;
        float v = 0.f;
        if (p >= 0 && p < kT) {
            float acc = bias;
            #pragma unroll
            for (int i = 0; i < 7; i++) {
                int x = p - 3 + i;
                float a = (x >= 0 && x < kT) ? au[x] : 0.f;
                acc = fmaf(wv[i], a, acc);
            }
            v = fmaxf(acc, 0.f);
        }
        s1[c1 * 5 + j] = v;
    }
    __syncthreads();
    int lane = tid & 31, warp = tid >> 5;
    for (int ii = 0; ii < 64; ii++) {
        int c2 = warp * 64 + ii;
        const float* wr = ew2 + (long)c2 * 1280;
        float acc = 0.f;
        #pragma unroll 4
        for (int kk = lane; kk < 1280; kk += 32)
            acc = fmaf(wr[kk], s1[kk], acc);
        #pragma unroll
        for (int o = 16; o > 0; o >>= 1) acc += __shfl_down_sync(0xffffffffu, acc, o);
        if (lane == 0) g_h2[(long)bs * 512 + c2] = fmaxf(acc + eb2[c2], 0.f);
    }
}

// ---------------- im2col for enc conv3 (k=3, p=1) ----------------
__global__ void k_im2col() {
    int m = blockIdx.x; int b = m / kS, s = m % kS;
    for (int kk = threadIdx.x; kk < 1536; kk += blockDim.x) {
        int c2 = kk / 3, j = kk % 3;
        int s2 = s - 1 + j;
        float v = (s2 >= 0 && s2 < kS) ? g_h2[(long)(b * kS + s2) * 512 + c2] : 0.f;
        g_X[(long)m * 1536 + kk] = v;
    }
}

// ---------------- f32x2 tiled GEMMs (64x64 tile, 128 threads, 8m x 4n / thread) -------
// Virtual A row m starts at A + (m/adiv)*aout + (m%adiv)*ain.
// blockIdx.z offsets: A+=z*zA, B+=z*zB, C+=z*zC, k range [z*zK, z*zK+Klen).
#define GEMM_PROLOG                                                          \
    __shared__ __align__(16) float As[16][72];                               \
    __shared__ __align__(16) float Bs[16][68];                               \
    int tid = threadIdx.x;                                                   \
    int m0 = blockIdx.y * 64, n0 = blockIdx.x * 64;                          \
    int tx = tid & 15, ty = tid >> 4;                                        \
    int lk = tid & 15, lm = tid >> 4;                                        \
    long kbase = (long)blockIdx.z * zK;                                      \
    ull acc[4][4];                                                           \
    _Pragma("unroll")                                                        \
    for (int i = 0; i < 4; i++)                                              \
        _Pragma("unroll")                                                    \
        for (int j = 0; j < 4; j++) acc[i][j] = 0ull;                        \
    long arow[8];                                                            \
    _Pragma("unroll")                                                        \
    for (int i = 0; i < 8; i++) {                                            \
        int m = m0 + lm + i * 8;                                             \
        arow[i] = (long)(m / adiv) * aout + (long)(m % adiv) * ain;          \
    }

#define GEMM_COMPUTE                                                         \
        __syncthreads();                                                     \
        _Pragma("unroll")                                                    \
        for (int k = 0; k < 16; k++) {                                       \
            ulonglong2 a01 = *(const ulonglong2*)&As[k][ty * 8];             \
            ulonglong2 a23 = *(const ulonglong2*)&As[k][ty * 8 + 4];         \
            float4 bv = *(const float4*)&Bs[k][tx * 4];                      \
            ull a_[4] = {a01.x, a01.y, a23.x, a23.y};                        \
            ull b_[4] = {dup2(bv.x), dup2(bv.y), dup2(bv.z), dup2(bv.w)};    \
            _Pragma("unroll")                                                \
            for (int i = 0; i < 4; i++)                                      \
                _Pragma("unroll")                                            \
                for (int j = 0; j < 4; j++)                                  \
                    fma2(acc[i][j], a_[i], b_[j]);                           \
        }                                                                    \
        __syncthreads();

#define GEMM_EPILOG                                                          \
    _Pragma("unroll")                                                        \
    for (int i = 0; i < 4; i++) {                                            \
        float lo0, hi0, lo1, hi1, lo2, hi2, lo3, hi3;                        \
        unpack2(acc[i][0], lo0, hi0); unpack2(acc[i][1], lo1, hi1);          \
        unpack2(acc[i][2], lo2, hi2); unpack2(acc[i][3], lo3, hi3);          \
        long mrow = m0 + ty * 8 + 2 * i;                                     \
        *(float4*)&C[mrow * N + n0 + tx * 4] = make_float4(lo0, lo1, lo2, lo3); \
        *(float4*)&C[(mrow + 1) * N + n0 + tx * 4] = make_float4(hi0, hi1, hi2, hi3); \
    }

// C[m,n] = sum_k Arow(m)[k] * B[n*ldb + k]   (B row-major [N, ldb>=K])
__global__ __launch_bounds__(128) void gemm_nt(
    const float* __restrict__ A, const float* __restrict__ Bm,
    float* __restrict__ C, int N, int Klen, int ldb,
    int adiv, long aout, long ain, long zA, long zB, long zC, long zK) {
    A += blockIdx.z * zA; Bm += blockIdx.z * zB; C += blockIdx.z * zC;
    GEMM_PROLOG
    for (int k0 = 0; k0 < Klen; k0 += 16) {
        long kg = kbase + k0 + lk;
        #pragma unroll
        for (int i = 0; i < 8; i++)
            As[lk][lm + i * 8] = A[arow[i] + kg];
        #pragma unroll
        for (int i = 0; i < 8; i++)
            Bs[lk][lm + i * 8] = Bm[(long)(n0 + lm + i * 8) * ldb + kg];
        GEMM_COMPUTE
    }
    GEMM_EPILOG
}

// C[m,n] = sum_k Arow(m)[k] * B[k*ldb + n]   (B row-major [K, ldb>=N])
__global__ __launch_bounds__(128) void gemm_nn(
    const float* __restrict__ A, const float* __restrict__ Bm,
    float* __restrict__ C, int N, int Klen, int ldb,
    int adiv, long aout, long ain, long zA, long zB, long zC, long zK) {
    A += blockIdx.z * zA; Bm += blockIdx.z * zB; C += blockIdx.z * zC;
    GEMM_PROLOG
    int nn = tid & 63, kk2 = tid >> 6;   // 2 k-rows per pass
    for (int k0 = 0; k0 < Klen; k0 += 16) {
        long kg = kbase + k0 + lk;
        #pragma unroll
        for (int i = 0; i < 8; i++)
            As[lk][lm + i * 8] = A[arow[i] + kg];
        #pragma unroll
        for (int i = 0; i < 8; i++) {
            int krow = kk2 + i * 2;
            Bs[krow][nn] = Bm[(kbase + k0 + krow) * (long)ldb + n0 + nn];
        }
        GEMM_COMPUTE
    }
    GEMM_EPILOG
}

// ---------------- VQ helpers ----------------
__global__ void k_embbias(const float* __restrict__ eb3) {
    int m = blockIdx.x;
    for (int n = threadIdx.x * 4; n < kCH3; n += blockDim.x * 4) {
        float4 v = *(const float4*)&g_C1[(long)m * kCH3 + n];
        float4 b = *(const float4*)&eb3[n];
        int k = n >> 9, d = n & 511;
        *(float4*)&g_emb[((long)k * kBS + m) * kDIM + d] =
            make_float4(v.x + b.x, v.y + b.y, v.z + b.z, v.w + b.w);
    }
}

__global__ void k_cbnorm(const float* __restrict__ cb) {
    int row = blockIdx.x * 8 + (threadIdx.x >> 5);
    int lane = threadIdx.x & 31;
    const float* p = cb + (long)row * kDIM;
    float acc = 0.f;
    for (int d = lane; d < kDIM; d += 32) { float v = p[d]; acc = fmaf(v, v, acc); }
    #pragma unroll
    for (int o = 16; o > 0; o >>= 1) acc += __shfl_down_sync(0xffffffffu, acc, o);
    if (!lane) g_cbn[row] = acc;
}

__global__ void k_argmin() {
    int row = blockIdx.x;                 // k*kBS + m
    int k = row / kBS;
    const float* sc = g_sc + (long)row * kVOC;
    const float* cn = g_cbn + k * kVOC;
    float best = 3.4e38f; int bi = 0;
    for (int v = threadIdx.x; v < kVOC; v += 256) {
        float d = cn[v] - 2.f * sc[v];
        if (d < best) { best = d; bi = v; }
    }
    __shared__ float sv[256]; __shared__ int si[256];
    sv[threadIdx.x] = best; si[threadIdx.x] = bi;
    __syncthreads();
    for (int st = 128; st > 0; st >>= 1) {
        if (threadIdx.x < st) {
            float o = sv[threadIdx.x + st]; int oi = si[threadIdx.x + st];
            if (o < sv[threadIdx.x] || (o == sv[threadIdx.x] && oi < si[threadIdx.x])) {
                sv[threadIdx.x] = o; si[threadIdx.x] = oi;
            }
        }
        __syncthreads();
    }
    if (!threadIdx.x) g_code[row] = si[0];
}

__global__ void k_gather(const float* __restrict__ cb) {
    int m = blockIdx.x;
    for (int n = threadIdx.x * 4; n < kCH3; n += blockDim.x * 4) {
        int k = n >> 9, d = n & 511;
        int code = g_code[k * kBS + m];
        *(float4*)&g_q[(long)m * kCH3 + n] =
            *(const float4*)&cb[((long)k * kVOC + code) * kDIM + d];
    }
}

// ---------------- decoder helpers ----------------
__global__ void k_w2r(const float* __restrict__ dw2) {
    long i = (long)blockIdx.x * blockDim.x + threadIdx.x;
    if (i < 256L * 2560) {
        int cp = (int)(i / 2560), r = (int)(i % 2560);
        int jj = r / 512, c = r % 512;
        g_W2r[i] = dw2[(long)cp * 2560 + c * 5 + jj];
    }
}

// a-window around 768s (sums the split-K partials of the conv_t GEMM)
__global__ void k_awin(const float* __restrict__ db1) {
    int m = blockIdx.x; int s = m % kS;
    const long SP = (long)kBS * 2560;
    for (int i = threadIdx.x; i < 13 * 512; i += blockDim.x) {
        int off = i / 512 - 6; int o = i & 511;
        long t = (long)s * kHOP + off;
        float v = 0.f;
        if (t >= 0 && t < kL) {
            if (off >= -2 && off <= 2) {
                long idx = (long)m * 2560 + o * 5 + (off + 2);
                float c2 = g_C2p[idx] + g_C2p[idx + SP] + g_C2p[idx + 2 * SP] + g_C2p[idx + 3 * SP];
                v = fmaxf(c2 + db1[o], 0.f);
            } else
                v = fmaxf(db1[o], 0.f);
        }
        g_awin[(long)m * 6656 + i] = v;
    }
}

__global__ void k_bg2(const float* __restrict__ dw2, const float* __restrict__ db1,
                      const float* __restrict__ db2) {
    int cp = blockIdx.x, tid = threadIdx.x;
    float acc = 0.f;
    for (int kk = tid; kk < 2560; kk += 256)
        acc = fmaf(dw2[(long)cp * 2560 + kk], fmaxf(db1[kk / 5], 0.f), acc);
    __shared__ float red[256];
    red[tid] = acc; __syncthreads();
    for (int st = 128; st; st >>= 1) { if (tid < st) red[tid] += red[tid + st]; __syncthreads(); }
    if (!tid) g_bg2[cp] = fmaxf(red[0] + db2[cp], 0.f);
}

__global__ void k_outbg(const float* __restrict__ dw3, const float* __restrict__ db3) {
    __shared__ float red[256];
    int c = threadIdx.x;
    float a = 0.f;
    #pragma unroll
    for (int j = 0; j < 7; j++) a += dw3[c * 7 + j];
    red[c] = a * g_bg2[c];
    __syncthreads();
    for (int st = 128; st; st >>= 1) { if (c < st) red[c] += red[c + st]; __syncthreads(); }
    if (!c) g_outbg = tanhf(red[0] + db3[0]);
}

__global__ void k_fill(float* __restrict__ out, long n) {
    long i = (long)blockIdx.x * 256 + threadIdx.x;
    if (i < n) out[i] = g_outbg;
}

__global__ __launch_bounds__(256) void k_final(
    float* __restrict__ out, const float* __restrict__ db2,
    const float* __restrict__ dw3, const float* __restrict__ db3) {
    int m = blockIdx.x; int b = m / kS, s = m % kS;
    int tid = threadIdx.x;
    int g = tid >> 4, l = tid & 15;
    int r3 = g - 7;
    long t = (long)s * kHOP + r3;
    bool active = (g < 15) && t >= 0 && t < kL;
    float acc = 0.f;
    if (g < 15) {
        for (int c = l; c < 256; c += 16) {
            #pragma unroll
            for (int j = 0; j < 7; j++) {
                int off = r3 - 3 + j;
                long tt = (long)s * kHOP + off;
                float a2;
                if (tt < 0 || tt >= kL) a2 = 0.f;
                else if (off >= -4 && off <= 4)
                    a2 = fmaxf(g_C3[((long)m * 9 + off + 4) * 256 + c] + db2[c], 0.f);
                else a2 = g_bg2[c];
                acc = fmaf(dw3[c * 7 + j], a2, acc);
            }
        }
    }
    #pragma unroll
    for (int o = 8; o > 0; o >>= 1) acc += __shfl_down_sync(0xffffffffu, acc, o, 16);
    if (active && l == 0) out[(long)b * kL + t] = tanhf(acc + db3[0]);
}

// ---------------- launch ----------------
extern "C" void kernel_launch(void* const* d_in, const int* in_sizes, int n_in,
                              void* d_out, int out_size) {
    const float* audio = (const float*)d_in[0];
    const float* cb    = (const float*)d_in[1];
    const float* ew1   = (const float*)d_in[2];
    const float* eb1   = (const float*)d_in[3];
    const float* ew2   = (const float*)d_in[4];
    const float* eb2   = (const float*)d_in[5];
    const float* ew3   = (const float*)d_in[6];
    const float* eb3   = (const float*)d_in[7];
    const float* dw1   = (const float*)d_in[8];
    const float* db1   = (const float*)d_in[9];
    const float* dw2   = (const float*)d_in[10];
    const float* db2   = (const float*)d_in[11];
    const float* dw3   = (const float*)d_in[12];
    const float* db3   = (const float*)d_in[13];
    float* out = (float*)d_out;

    void *pX, *pC1, *pEmb, *pSc, *pQ, *pC2p, *pAwin, *pW2r, *pC3;
    cudaGetSymbolAddress(&pX, g_X);
    cudaGetSymbolAddress(&pC1, g_C1);
    cudaGetSymbolAddress(&pEmb, g_emb);
    cudaGetSymbolAddress(&pSc, g_sc);
    cudaGetSymbolAddress(&pQ, g_q);
    cudaGetSymbolAddress(&pC2p, g_C2p);
    cudaGetSymbolAddress(&pAwin, g_awin);
    cudaGetSymbolAddress(&pW2r, g_W2r);
    cudaGetSymbolAddress(&pC3, g_C3);

    const int BIG = 1 << 30;

    // encoder
    k_enc12<<<kBS, 256>>>(audio, ew1, eb1, ew2, eb2);
    k_im2col<<<kBS, 256>>>();
    gemm_nt<<<dim3(kCH3 / 64, kBS / 64, 1), 128>>>(
        (const float*)pX, ew3, (float*)pC1, kCH3, 1536, 1536,
        BIG, 0, 1536, 0, 0, 0, 0);
    k_embbias<<<kBS, 256>>>(eb3);

    // VQ (kept fully fp32: argmin robustness)
    k_cbnorm<<<kNCB * kVOC / 8, 256>>>(cb);
    gemm_nt<<<dim3(kVOC / 64, kBS / 64, kNCB), 128>>>(
        (const float*)pEmb, cb, (float*)pSc, kVOC, kDIM, kDIM,
        BIG, 0, kDIM, (long)kBS * kDIM, (long)kVOC * kDIM, (long)kBS * kVOC, 0);
    k_argmin<<<kNCB * kBS, 256>>>();
    k_gather<<<kBS, 256>>>(cb);

    // decoder: conv_transpose specials, split-K=4 (dw1 is the NN GEMM B matrix)
    gemm_nn<<<dim3(2560 / 64, kBS / 64, kSPLIT), 128>>>(
        (const float*)pQ, dw1, (float*)pC2p, 2560, kCH3 / kSPLIT, 2560,
        BIG, 0, kCH3, 0, 0, (long)kBS * 2560, kCH3 / kSPLIT);

    // decoder conv2 specials over sliding windows
    k_w2r<<<(256 * 2560 + 255) / 256, 256>>>(dw2);
    k_awin<<<kBS, 256>>>(db1);
    gemm_nt<<<dim3(256 / 64, kBS * 9 / 64, 1), 128>>>(
        (const float*)pAwin, (const float*)pW2r, (float*)pC3, 256, 2560, 2560,
        9, 6656, 512, 0, 0, 0, 0);

    // background + final conv3 specials
    k_bg2<<<256, 256>>>(dw2, db1, db2);
    k_outbg<<<1, 256>>>(dw3, db3);
    k_fill<<<(int)((kB * kL + 255) / 256), 256>>>(out, kB * kL);
    k_final<<<kBS, 256>>>(out, db2, dw3, db3);
}

// round 3
// speedup vs baseline: 1.6546x; 1.2509x over previous
#include <cuda_runtime.h>
#include <math.h>

typedef unsigned long long ull;

// ---------------- problem constants ----------------
constexpr int kB   = 2;
constexpr int kT   = 98304;
constexpr int kS   = 128;
constexpr int kHOP = 768;
constexpr int kNCB = 14;
constexpr int kDIM = 512;
constexpr int kVOC = 1024;
constexpr int kCH3 = kNCB * kDIM;   // 7168
constexpr long kL  = 97537;
constexpr int kBS  = kB * kS;       // 256
constexpr int kSPLIT = 4;
constexpr long BIGL = 1L << 40;

// ---------------- device scratch ----------------
__device__ float g_S1  [kBS * 1280];            // conv1 windows [m][c1*5+j]
__device__ float g_h2  [kBS * 512];
__device__ float g_X   [kBS * 1536];
__device__ float g_emb [kNCB * kBS * kDIM];     // [k][m][d]
__device__ float g_sc  [(long)kNCB * kBS * kVOC];
__device__ float g_cbn [kNCB * kVOC];
__device__ int   g_code[kNCB * kBS];
__device__ float g_q   [kBS * kCH3];
__device__ float g_C2p [kSPLIT * kBS * 2560];
__device__ float g_awin[kBS * 13 * 512];
__device__ float g_W2r [256 * 2560];
__device__ float g_C3  [kBS * 9 * 256];         // relu(conv2+db2) at specials
__device__ float g_bg2 [256];
__device__ float g_outbg;

// ---------------- f32x2 helpers ----------------
__device__ __forceinline__ void fma2(ull& acc, ull a, ull b) {
    asm("fma.rn.f32x2 %0, %1, %2, %0;" : "+l"(acc) : "l"(a), "l"(b));
}
__device__ __forceinline__ ull dup2(float x) {
    ull r; asm("mov.b64 %0, {%1, %1};" : "=l"(r) : "f"(x)); return r;
}
__device__ __forceinline__ void unpack2(ull v, float& lo, float& hi) {
    asm("mov.b64 {%0, %1}, %2;" : "=f"(lo), "=f"(hi) : "l"(v));
}

// ---------------- conv1 window builder ----------------
__global__ __launch_bounds__(256) void k_prep1(
    const float* __restrict__ audio, const float* __restrict__ ew1,
    const float* __restrict__ eb1) {
    int m = blockIdx.x; int b = m / kS, s = m % kS;
    int c1 = threadIdx.x;
    float wv[7];
    #pragma unroll
    for (int i = 0; i < 7; i++) wv[i] = ew1[c1 * 7 + i];
    float bias = eb1[c1];
    const float* au = audio + (long)b * kT;
    #pragma unroll
    for (int j = 0; j < 5; j++) {
        int p = s * kHOP - 2 + j;
        float v = 0.f;
        if (p >= 0 && p < kT) {
            float acc = bias;
            #pragma unroll
            for (int i = 0; i < 7; i++) {
                int x = p - 3 + i;
                float a = (x >= 0 && x < kT) ? au[x] : 0.f;
                acc = fmaf(wv[i], a, acc);
            }
            v = fmaxf(acc, 0.f);
        }
        g_S1[(long)m * 1280 + c1 * 5 + j] = v;
    }
}

// ---------------- im2col for enc conv3 (k=3, p=1) ----------------
__global__ void k_im2col() {
    int m = blockIdx.x; int b = m / kS, s = m % kS;
    for (int kk = threadIdx.x; kk < 1536; kk += blockDim.x) {
        int c2 = kk / 3, j = kk % 3;
        int s2 = s - 1 + j;
        float v = (s2 >= 0 && s2 < kS) ? g_h2[(long)(b * kS + s2) * 512 + c2] : 0.f;
        g_X[(long)m * 1536 + kk] = v;
    }
}

// ============== double-buffered f32x2 GEMM (64x64 tile, 128 thr) ==============
// Virtual A row m starts at A + (m/adiv)*aout + (m%adiv)*ain.
// z offsets: A+=z*zA, B+=z*zB, C+=z*zC, k range starts at z*zK.
// C write: Cb = C + (n0/cdiv)*cout; addr = Cb + mrow*ldc + n0%cdiv + col.
// Optional bias[n] (global n) and relu.

#define GEMM_PROLOG                                                          \
    __shared__ __align__(16) float As[2][16][72];                            \
    __shared__ __align__(16) float Bs[2][16][68];                            \
    int tid = threadIdx.x;                                                   \
    int m0 = blockIdx.y * 64, n0 = blockIdx.x * 64;                          \
    int tx = tid & 15, ty = tid >> 4;                                        \
    long kbase = (long)blockIdx.z * zK;                                      \
    ull acc[4][4];                                                           \
    _Pragma("unroll")                                                        \
    for (int i = 0; i < 4; i++)                                              \
        _Pragma("unroll")                                                    \
        for (int j = 0; j < 4; j++) acc[i][j] = 0ull;                        \
    int am = tid >> 1;                                                       \
    int akq = (tid & 1) * 8;                                                 \
    int mm = m0 + am;                                                        \
    long arowA = (long)(mm / adiv) * aout + (long)(mm % adiv) * ain;         \
    float4 ra0, ra1, rb0, rb1;

#define LOAD_A(k0v) {                                                        \
    long kg = kbase + (k0v) + akq;                                           \
    ra0 = *(const float4*)&A[arowA + kg];                                    \
    ra1 = *(const float4*)&A[arowA + kg + 4]; }

#define STORE_A(bufv) {                                                      \
    As[bufv][akq + 0][am] = ra0.x; As[bufv][akq + 1][am] = ra0.y;            \
    As[bufv][akq + 2][am] = ra0.z; As[bufv][akq + 3][am] = ra0.w;            \
    As[bufv][akq + 4][am] = ra1.x; As[bufv][akq + 5][am] = ra1.y;            \
    As[bufv][akq + 6][am] = ra1.z; As[bufv][akq + 7][am] = ra1.w; }

#define GEMM_COMPUTE(bufv)                                                   \
    _Pragma("unroll")                                                        \
    for (int k = 0; k < 16; k++) {                                           \
        ulonglong2 a01 = *(const ulonglong2*)&As[bufv][k][ty * 8];           \
        ulonglong2 a23 = *(const ulonglong2*)&As[bufv][k][ty * 8 + 4];       \
        float4 bv = *(const float4*)&Bs[bufv][k][tx * 4];                    \
        ull a_[4] = {a01.x, a01.y, a23.x, a23.y};                            \
        ull b_[4] = {dup2(bv.x), dup2(bv.y), dup2(bv.z), dup2(bv.w)};        \
        _Pragma("unroll")                                                    \
        for (int i = 0; i < 4; i++)                                          \
            _Pragma("unroll")                                                \
            for (int j = 0; j < 4; j++)                                      \
                fma2(acc[i][j], a_[i], b_[j]);                               \
    }

#define GEMM_MAIN(LOADB, STOREB)                                             \
    LOAD_A(0) LOADB(0)                                                       \
    STORE_A(0) STOREB(0)                                                     \
    __syncthreads();                                                         \
    int T = Klen / 16;                                                       \
    for (int t = 0; t < T; t++) {                                            \
        int cur = t & 1;                                                     \
        if (t + 1 < T) { LOAD_A((t + 1) * 16) LOADB((t + 1) * 16) }          \
        GEMM_COMPUTE(cur)                                                    \
        if (t + 1 < T) { STORE_A(1 - cur) STOREB(1 - cur) }                  \
        __syncthreads();                                                     \
    }

#define GEMM_EPILOG                                                          \
    float4 bv4 = make_float4(0.f, 0.f, 0.f, 0.f);                            \
    if (bias) bv4 = *(const float4*)&bias[n0 + tx * 4];                      \
    float* Cb = C + (long)(n0 / cdiv) * cout;                                \
    int nc = (int)(n0 % cdiv) + tx * 4;                                      \
    _Pragma("unroll")                                                        \
    for (int i = 0; i < 4; i++) {                                            \
        float lo0, hi0, lo1, hi1, lo2, hi2, lo3, hi3;                        \
        unpack2(acc[i][0], lo0, hi0); unpack2(acc[i][1], lo1, hi1);          \
        unpack2(acc[i][2], lo2, hi2); unpack2(acc[i][3], lo3, hi3);          \
        float4 v0 = make_float4(lo0 + bv4.x, lo1 + bv4.y, lo2 + bv4.z, lo3 + bv4.w); \
        float4 v1 = make_float4(hi0 + bv4.x, hi1 + bv4.y, hi2 + bv4.z, hi3 + bv4.w); \
        if (relu) {                                                          \
            v0.x = fmaxf(v0.x, 0.f); v0.y = fmaxf(v0.y, 0.f);                \
            v0.z = fmaxf(v0.z, 0.f); v0.w = fmaxf(v0.w, 0.f);                \
            v1.x = fmaxf(v1.x, 0.f); v1.y = fmaxf(v1.y, 0.f);                \
            v1.z = fmaxf(v1.z, 0.f); v1.w = fmaxf(v1.w, 0.f);                \
        }                                                                    \
        long mrow = m0 + ty * 8 + 2 * i;                                     \
        *(float4*)&Cb[mrow * ldc + nc] = v0;                                 \
        *(float4*)&Cb[(mrow + 1) * ldc + nc] = v1;                           \
    }

// B row-major [N, ldb]: C[m,n] = sum_k A(m)[k] * B[n][k]
__global__ __launch_bounds__(128) void gemm_nt(
    const float* __restrict__ A, const float* __restrict__ Bm,
    float* __restrict__ C, int Klen, int ldb,
    long adiv, long aout, long ain, long zA, long zB, long zC, long zK,
    int ldc, long cdiv, long cout, const float* __restrict__ bias, int relu) {
    A += blockIdx.z * zA; Bm += blockIdx.z * zB; C += blockIdx.z * zC;
    GEMM_PROLOG
    int bn = tid >> 1;
    int bkq = (tid & 1) * 8;
#define LOAD_B_NT(k0v) {                                                     \
    long kg = kbase + (k0v) + bkq;                                           \
    const float* bp = &Bm[(long)(n0 + bn) * ldb + kg];                       \
    rb0 = *(const float4*)bp; rb1 = *(const float4*)(bp + 4); }
#define STORE_B_NT(bufv) {                                                   \
    Bs[bufv][bkq + 0][bn] = rb0.x; Bs[bufv][bkq + 1][bn] = rb0.y;            \
    Bs[bufv][bkq + 2][bn] = rb0.z; Bs[bufv][bkq + 3][bn] = rb0.w;            \
    Bs[bufv][bkq + 4][bn] = rb1.x; Bs[bufv][bkq + 5][bn] = rb1.y;            \
    Bs[bufv][bkq + 6][bn] = rb1.z; Bs[bufv][bkq + 7][bn] = rb1.w; }
    GEMM_MAIN(LOAD_B_NT, STORE_B_NT)
    GEMM_EPILOG
}

// B row-major [K, ldb]: C[m,n] = sum_k A(m)[k] * B[k][n]
__global__ __launch_bounds__(128) void gemm_nn(
    const float* __restrict__ A, const float* __restrict__ Bm,
    float* __restrict__ C, int Klen, int ldb,
    long adiv, long aout, long ain, long zA, long zB, long zC, long zK,
    int ldc, long cdiv, long cout, const float* __restrict__ bias, int relu) {
    A += blockIdx.z * zA; Bm += blockIdx.z * zB; C += blockIdx.z * zC;
    GEMM_PROLOG
    int bk = tid >> 3;
    int bc = (tid & 7) * 4;
#define LOAD_B_NN(k0v) {                                                     \
    long kr = kbase + (k0v) + bk;                                            \
    const float* bp = &Bm[kr * (long)ldb + n0 + bc];                         \
    rb0 = *(const float4*)bp; rb1 = *(const float4*)(bp + 32); }
#define STORE_B_NN(bufv) {                                                   \
    *(float4*)&Bs[bufv][bk][bc] = rb0;                                       \
    *(float4*)&Bs[bufv][bk][bc + 32] = rb1; }
    GEMM_MAIN(LOAD_B_NN, STORE_B_NN)
    GEMM_EPILOG
}

// ---------------- VQ helpers ----------------
__global__ void k_cbnorm(const float* __restrict__ cb) {
    int row = blockIdx.x * 8 + (threadIdx.x >> 5);
    int lane = threadIdx.x & 31;
    const float* p = cb + (long)row * kDIM;
    float acc = 0.f;
    for (int d = lane; d < kDIM; d += 32) { float v = p[d]; acc = fmaf(v, v, acc); }
    #pragma unroll
    for (int o = 16; o > 0; o >>= 1) acc += __shfl_down_sync(0xffffffffu, acc, o);
    if (!lane) g_cbn[row] = acc;
}

__global__ void k_argmin() {
    int row = blockIdx.x;
    int k = row / kBS;
    const float* sc = g_sc + (long)row * kVOC;
    const float* cn = g_cbn + k * kVOC;
    float best = 3.4e38f; int bi = 0;
    for (int v = threadIdx.x; v < kVOC; v += 256) {
        float d = cn[v] - 2.f * sc[v];
        if (d < best) { best = d; bi = v; }
    }
    __shared__ float sv[256]; __shared__ int si[256];
    sv[threadIdx.x] = best; si[threadIdx.x] = bi;
    __syncthreads();
    for (int st = 128; st > 0; st >>= 1) {
        if (threadIdx.x < st) {
            float o = sv[threadIdx.x + st]; int oi = si[threadIdx.x + st];
            if (o < sv[threadIdx.x] || (o == sv[threadIdx.x] && oi < si[threadIdx.x])) {
                sv[threadIdx.x] = o; si[threadIdx.x] = oi;
            }
        }
        __syncthreads();
    }
    if (!threadIdx.x) g_code[row] = si[0];
}

__global__ void k_gather(const float* __restrict__ cb) {
    int m = blockIdx.x;
    for (int n = threadIdx.x * 4; n < kCH3; n += blockDim.x * 4) {
        int k = n >> 9, d = n & 511;
        int code = g_code[k * kBS + m];
        *(float4*)&g_q[(long)m * kCH3 + n] =
            *(const float4*)&cb[((long)k * kVOC + code) * kDIM + d];
    }
}

// ---------------- decoder helpers ----------------
__global__ void k_w2r(const float* __restrict__ dw2) {
    long i = (long)blockIdx.x * blockDim.x + threadIdx.x;
    if (i < 256L * 2560) {
        int cp = (int)(i / 2560), r = (int)(i % 2560);
        int jj = r / 512, c = r % 512;
        g_W2r[i] = dw2[(long)cp * 2560 + c * 5 + jj];
    }
}

__global__ void k_awin(const float* __restrict__ db1) {
    int m = blockIdx.x; int s = m % kS;
    const long SP = (long)kBS * 2560;
    for (int i = threadIdx.x; i < 13 * 512; i += blockDim.x) {
        int off = i / 512 - 6; int o = i & 511;
        long t = (long)s * kHOP + off;
        float v = 0.f;
        if (t >= 0 && t < kL) {
            if (off >= -2 && off <= 2) {
                long idx = (long)m * 2560 + o * 5 + (off + 2);
                float c2 = g_C2p[idx] + g_C2p[idx + SP] + g_C2p[idx + 2 * SP] + g_C2p[idx + 3 * SP];
                v = fmaxf(c2 + db1[o], 0.f);
            } else
                v = fmaxf(db1[o], 0.f);
        }
        g_awin[(long)m * 6656 + i] = v;
    }
}

__global__ void k_bg2(const float* __restrict__ dw2, const float* __restrict__ db1,
                      const float* __restrict__ db2) {
    int cp = blockIdx.x, tid = threadIdx.x;
    float acc = 0.f;
    for (int kk = tid; kk < 2560; kk += 256)
        acc = fmaf(dw2[(long)cp * 2560 + kk], fmaxf(db1[kk / 5], 0.f), acc);
    __shared__ float red[256];
    red[tid] = acc; __syncthreads();
    for (int st = 128; st; st >>= 1) { if (tid < st) red[tid] += red[tid + st]; __syncthreads(); }
    if (!tid) g_bg2[cp] = fmaxf(red[0] + db2[cp], 0.f);
}

__global__ void k_outbg(const float* __restrict__ dw3, const float* __restrict__ db3) {
    __shared__ float red[256];
    int c = threadIdx.x;
    float a = 0.f;
    #pragma unroll
    for (int j = 0; j < 7; j++) a += dw3[c * 7 + j];
    red[c] = a * g_bg2[c];
    __syncthreads();
    for (int st = 128; st; st >>= 1) { if (c < st) red[c] += red[c + st]; __syncthreads(); }
    if (!c) g_outbg = tanhf(red[0] + db3[0]);
}

__global__ void k_fill(float* __restrict__ out, long n) {
    long i = (long)blockIdx.x * 256 + threadIdx.x;
    if (i < n) out[i] = g_outbg;
}

__global__ __launch_bounds__(256) void k_final(
    float* __restrict__ out,
    const float* __restrict__ dw3, const float* __restrict__ db3) {
    int m = blockIdx.x; int b = m / kS, s = m % kS;
    int tid = threadIdx.x;
    int g = tid >> 4, l = tid & 15;
    int r3 = g - 7;
    long t = (long)s * kHOP + r3;
    bool active = (g < 15) && t >= 0 && t < kL;
    float acc = 0.f;
    if (g < 15) {
        for (int c = l; c < 256; c += 16) {
            #pragma unroll
            for (int j = 0; j < 7; j++) {
                int off = r3 - 3 + j;
                long tt = (long)s * kHOP + off;
                float a2;
                if (tt < 0 || tt >= kL) a2 = 0.f;
                else if (off >= -4 && off <= 4)
                    a2 = g_C3[((long)m * 9 + off + 4) * 256 + c];   // already relu(conv2+db2)
                else a2 = g_bg2[c];
                acc = fmaf(dw3[c * 7 + j], a2, acc);
            }
        }
    }
    #pragma unroll
    for (int o = 8; o > 0; o >>= 1) acc += __shfl_down_sync(0xffffffffu, acc, o, 16);
    if (active && l == 0) out[(long)b * kL + t] = tanhf(acc + db3[0]);
}

// ---------------- launch ----------------
extern "C" void kernel_launch(void* const* d_in, const int* in_sizes, int n_in,
                              void* d_out, int out_size) {
    const float* audio = (const float*)d_in[0];
    const float* cb    = (const float*)d_in[1];
    const float* ew1   = (const float*)d_in[2];
    const float* eb1   = (const float*)d_in[3];
    const float* ew2   = (const float*)d_in[4];
    const float* eb2   = (const float*)d_in[5];
    const float* ew3   = (const float*)d_in[6];
    const float* eb3   = (const float*)d_in[7];
    const float* dw1   = (const float*)d_in[8];
    const float* db1   = (const float*)d_in[9];
    const float* dw2   = (const float*)d_in[10];
    const float* db2   = (const float*)d_in[11];
    const float* dw3   = (const float*)d_in[12];
    const float* db3   = (const float*)d_in[13];
    float* out = (float*)d_out;

    void *pS1, *pH2, *pX, *pEmb, *pSc, *pQ, *pC2p, *pAwin, *pW2r, *pC3;
    cudaGetSymbolAddress(&pS1, g_S1);
    cudaGetSymbolAddress(&pH2, g_h2);
    cudaGetSymbolAddress(&pX, g_X);
    cudaGetSymbolAddress(&pEmb, g_emb);
    cudaGetSymbolAddress(&pSc, g_sc);
    cudaGetSymbolAddress(&pQ, g_q);
    cudaGetSymbolAddress(&pC2p, g_C2p);
    cudaGetSymbolAddress(&pAwin, g_awin);
    cudaGetSymbolAddress(&pW2r, g_W2r);
    cudaGetSymbolAddress(&pC3, g_C3);

    // weight-only prep (no deps)
    k_cbnorm<<<kNCB * kVOC / 8, 256>>>(cb);
    k_w2r<<<(256 * 2560 + 255) / 256, 256>>>(dw2);
    k_bg2<<<256, 256>>>(dw2, db1, db2);
    k_outbg<<<1, 256>>>(dw3, db3);
    k_fill<<<(int)((kB * kL + 255) / 256), 256>>>(out, kB * kL);

    // encoder: conv1 windows -> GEMM conv2 (bias+relu) -> im2col -> GEMM conv3
    k_prep1<<<kBS, 256>>>(audio, ew1, eb1);
    gemm_nt<<<dim3(512 / 64, kBS / 64, 1), 128>>>(
        (const float*)pS1, ew2, (float*)pH2, 1280, 1280,
        BIGL, 0, 1280, 0, 0, 0, 0, 512, BIGL, 0, eb2, 1);
    k_im2col<<<kBS, 256>>>();
    // writes straight into g_emb [k][m][d] layout with eb3 fused
    gemm_nt<<<dim3(kCH3 / 64, kBS / 64, 1), 128>>>(
        (const float*)pX, ew3, (float*)pEmb, 1536, 1536,
        BIGL, 0, 1536, 0, 0, 0, 0, 512, 512, (long)kBS * 512, eb3, 0);

    // VQ
    gemm_nt<<<dim3(kVOC / 64, kBS / 64, kNCB), 128>>>(
        (const float*)pEmb, cb, (float*)pSc, kDIM, kDIM,
        BIGL, 0, kDIM, (long)kBS * kDIM, (long)kVOC * kDIM, (long)kBS * kVOC, 0,
        kVOC, BIGL, 0, nullptr, 0);
    k_argmin<<<kNCB * kBS, 256>>>();
    k_gather<<<kBS, 256>>>(cb);

    // decoder conv_transpose specials, split-K=4
    gemm_nn<<<dim3(2560 / 64, kBS / 64, kSPLIT), 128>>>(
        (const float*)pQ, dw1, (float*)pC2p, kCH3 / kSPLIT, 2560,
        BIGL, 0, kCH3, 0, 0, (long)kBS * 2560, kCH3 / kSPLIT,
        2560, BIGL, 0, nullptr, 0);

    // decoder conv2 specials (bias db2 + relu fused)
    k_awin<<<kBS, 256>>>(db1);
    gemm_nt<<<dim3(256 / 64, kBS * 9 / 64, 1), 128>>>(
        (const float*)pAwin, (const float*)pW2r, (float*)pC3, 2560, 2560,
        9, 6656, 512, 0, 0, 0, 0, 256, BIGL, 0, db2, 1);

    // final conv3 specials
    k_final<<<kBS, 256>>>(out, dw3, db3);
}